// round 12
// baseline (speedup 1.0000x reference)
#include <cuda_runtime.h>
#include <cuda_fp16.h>
#include <math.h>
#include <stdint.h>

// ---------------------------------------------------------------------------
// EfficientSelfAttention (PVT SRA): B=4, N=4096 (64x64), C=512, heads=8,
// head_dim=64, SR=2 -> N_kv=1024.  fp16 m16n8k16 mma.sync (fp32 accum).
// Round 12: Q-proj + conv merged into one launch (shared wave tail);
// conv split-K=2; otherwise round-11 structure.
// ---------------------------------------------------------------------------

__device__ __half  g_xt[8388608];   // x as half [16384][512]
__device__ float   g_xr[2097152];   // conv partial z=0 (fp32, +bias)
__device__ float   g_xr2[2097152];  // conv partial z=1
__device__ __half  g_xrh[2097152];  // LN output half
__device__ __half  g_k[2097152];    // [bh][m][d]
__device__ __half  g_v[2097152];    // TRANSPOSED: [bh][d][m]
__device__ __half  g_att[8388608];  // [b,n, h*64+d]
__device__ uint32_t g_q[4194304];   // Q in fp16 A-fragment order (log2-scaled)
__device__ __half  g_wq[262144];    // W^T [N][K]
__device__ __half  g_wkv[524288];
__device__ __half  g_wp[262144];
__device__ __half  g_wsr[1048576];

#define QSCALE 0.18033688011112042f   // 0.125 * log2(e)

__device__ __forceinline__ uint32_t pack2(float a, float b) {
    __half2 h = __floats2half2_rn(a, b);
    return *(uint32_t*)&h;
}
__device__ __forceinline__ uint32_t h2ex2(uint32_t x) {
    uint32_t r;
    asm("ex2.approx.f16x2 %0, %1;" : "=r"(r) : "r"(x));
    return r;
}
__device__ __forceinline__ float2 h2f2(uint32_t x) {
    __half2 h = *(__half2*)&x;
    return __half22float2(h);
}

__device__ __forceinline__ void mma16(float* c, const uint32_t* a, const uint32_t* b) {
    asm("mma.sync.aligned.m16n8k16.row.col.f32.f16.f16.f32 "
        "{%0,%1,%2,%3}, {%4,%5,%6,%7}, {%8,%9}, {%0,%1,%2,%3};"
        : "+f"(c[0]), "+f"(c[1]), "+f"(c[2]), "+f"(c[3])
        : "r"(a[0]), "r"(a[1]), "r"(a[2]), "r"(a[3]), "r"(b[0]), "r"(b[1]));
}

__device__ __forceinline__ void cp16(uint32_t dst, const void* src) {
    asm volatile("cp.async.cg.shared.global [%0], [%1], 16;" :: "r"(dst), "l"(src));
}
__device__ __forceinline__ void cp_commit() {
    asm volatile("cp.async.commit_group;");
}
template <int N>
__device__ __forceinline__ void cp_wait() {
    asm volatile("cp.async.wait_group %0;" :: "n"(N));
}

// ---------------------------------------------------------------------------
// Merged pre-pass: blocks [0,8192) convert x -> half; [8192,10240) transpose
// weights fp32 [K][N] -> half [N][K].
// ---------------------------------------------------------------------------
__global__ void __launch_bounds__(256) prepass(
    const float4* __restrict__ x,
    const float* __restrict__ wq, const float* __restrict__ wkv,
    const float* __restrict__ wp, const float* __restrict__ wsr)
{
    __shared__ float tile[32][33];
    if (blockIdx.x < 8192) {
        int i = blockIdx.x * 256 + threadIdx.x;
        float4 v = x[i];
        uint2 o;
        o.x = pack2(v.x, v.y);
        o.y = pack2(v.z, v.w);
        *(uint2*)(g_xt + (size_t)i * 4) = o;
        return;
    }
    int t = blockIdx.x - 8192;
    const float* src; __half* dst; int K, N, tk, tn;
    if (t < 256)       { src = wq;  dst = g_wq;  K = 512;  N = 512;  tk = t >> 4; tn = t & 15; }
    else if (t < 768)  { t -= 256;  src = wkv; dst = g_wkv; K = 512;  N = 1024; tk = t >> 5; tn = t & 31; }
    else if (t < 1024) { t -= 768;  src = wp;  dst = g_wp;  K = 512;  N = 512;  tk = t >> 4; tn = t & 15; }
    else               { t -= 1024; src = wsr; dst = g_wsr; K = 2048; N = 512;  tk = t >> 4; tn = t & 15; }

    int tx = threadIdx.x & 31, ty = threadIdx.x >> 5;
    int k0 = tk * 32, n0 = tn * 32;
    #pragma unroll
    for (int i = 0; i < 4; i++)
        tile[tx][ty + 8 * i] = src[(size_t)(k0 + ty + 8 * i) * N + n0 + tx];
    __syncthreads();
    #pragma unroll
    for (int i = 0; i < 4; i++) {
        int row = ty + 8 * i;
        dst[(size_t)(n0 + row) * K + k0 + tx] = __float2half_rn(tile[row][tx]);
    }
}

// ---------------------------------------------------------------------------
// Wide GEMM body: tile 128x256, BK=32, 3-stage ring, 8 warps (2x4),
// warp tile 64x64.  MODE 0: -> g_q fragment order; MODE 3: -> Cout fp32.
// smem u32: A[3][128][20] @0 | B[3][256][20] @7680  (92160 B)
// ---------------------------------------------------------------------------
template <int MODE>
__device__ __forceinline__ void wide_body(
    uint32_t* smem, int m0, int n0,
    const float* __restrict__ bias, float* __restrict__ Cout)
{
    const int OB = 3 * 128 * 20;
    const int K = 512;
    const int tid = threadIdx.x, lane = tid & 31, warp = tid >> 5;
    const int wm = warp >> 2, wn = warp & 3;
    const int l2 = lane >> 2, l4 = lane & 3;

    const __half* Ap = (MODE == 3) ? g_att : g_xt;
    const __half* Bp = (MODE == 3) ? g_wp : g_wq;

    const uint32_t sbase = (uint32_t)__cvta_generic_to_shared(smem);

    float acc[4][8][4] = {};

    auto load_tiles = [&](int s, int k0) {
        #pragma unroll
        for (int u = 0; u < 2; u++) {
            int e = u * 256 + tid;
            int row = e >> 2, cw = e & 3;
            cp16(sbase + (uint32_t)(s * 2560 + row * 20 + cw * 4) * 4,
                 Ap + (size_t)(m0 + row) * K + k0 + cw * 8);
        }
        #pragma unroll
        for (int u = 0; u < 4; u++) {
            int e = u * 256 + tid;
            int row = e >> 2, cw = e & 3;
            cp16(sbase + (uint32_t)(OB + s * 5120 + row * 20 + cw * 4) * 4,
                 Bp + (size_t)(n0 + row) * K + k0 + cw * 8);
        }
    };

    const int KT = K >> 5;
    load_tiles(0, 0);
    cp_commit();
    load_tiles(1, 32);
    cp_commit();

    for (int kt = 0; kt < KT; kt++) {
        if (kt < KT - 1) { cp_wait<1>(); } else { cp_wait<0>(); }
        __syncthreads();
        if (kt + 2 < KT) {
            load_tiles((kt + 2) % 3, (kt + 2) * 32);
            cp_commit();
        }
        const int stage = kt % 3;

        const uint32_t* Ab = smem + stage * 2560;
        const uint32_t* Bb = smem + OB + stage * 5120;
        #pragma unroll
        for (int j = 0; j < 2; j++) {
            uint32_t a[4][4], bf[8][2];
            #pragma unroll
            for (int mt = 0; mt < 4; mt++) {
                int r = wm * 64 + mt * 16 + l2;
                a[mt][0] = Ab[r * 20 + j * 8 + l4];
                a[mt][1] = Ab[(r + 8) * 20 + j * 8 + l4];
                a[mt][2] = Ab[r * 20 + j * 8 + l4 + 4];
                a[mt][3] = Ab[(r + 8) * 20 + j * 8 + l4 + 4];
            }
            #pragma unroll
            for (int nt = 0; nt < 8; nt++) {
                int col = wn * 64 + nt * 8 + l2;
                bf[nt][0] = Bb[col * 20 + j * 8 + l4];
                bf[nt][1] = Bb[col * 20 + j * 8 + l4 + 4];
            }
            #pragma unroll
            for (int mt = 0; mt < 4; mt++)
                #pragma unroll
                for (int nt = 0; nt < 8; nt++)
                    mma16(acc[mt][nt], a[mt], bf[nt]);
        }
        __syncthreads();
    }

    #pragma unroll
    for (int mt = 0; mt < 4; mt++) {
        #pragma unroll
        for (int nt = 0; nt < 8; nt++) {
            int r = m0 + wm * 64 + mt * 16 + l2;
            int c = n0 + wn * 64 + nt * 8 + l4 * 2;
            float b0 = bias[c], b1 = bias[c + 1];
            float v00 = acc[mt][nt][0] + b0, v01 = acc[mt][nt][1] + b1;
            float v10 = acc[mt][nt][2] + b0, v11 = acc[mt][nt][3] + b1;
            if (MODE == 0) {
                int b_ = r >> 12, nq = r & 4095;
                int h = c >> 6, d = c & 63;
                int bh = b_ * 8 + h, ntile = nq >> 4;
                int j = d >> 4, wsel = (d >> 3) & 1;
                size_t base = (((size_t)(bh * 256 + ntile) * 4 + j) * 32 + lane) * 4 + wsel * 2;
                g_q[base]     = pack2(v00 * QSCALE, v01 * QSCALE);
                g_q[base + 1] = pack2(v10 * QSCALE, v11 * QSCALE);
            } else {
                *(float2*)(Cout + (size_t)r * 512 + c) = make_float2(v00, v01);
                *(float2*)(Cout + (size_t)(r + 8) * 512 + c) = make_float2(v10, v11);
            }
        }
    }
}

// ---------------------------------------------------------------------------
// Conv GEMM body (patch gather), tile 128x128, split-K half (Kblk=1024),
// 3-stage ring, warp tile 32x64. z=0 -> g_xr (+bias), z=1 -> g_xr2.
// smem u32: A[3][128][20] @0 | B[3][128][20] @7680  (61440 B)
// ---------------------------------------------------------------------------
__device__ __forceinline__ void conv_body(
    uint32_t* smem, int m0, int n0, int z, const float* __restrict__ bias)
{
    const int OB = 3 * 128 * 20;
    const int Kfull = 2048;
    const int kz0 = z * 1024;
    const int tid = threadIdx.x, lane = tid & 31, warp = tid >> 5;
    const int wm = warp >> 1, wn = warp & 1;
    const int l2 = lane >> 2, l4 = lane & 3;

    const uint32_t sbase = (uint32_t)__cvta_generic_to_shared(smem);

    float acc[2][8][4] = {};

    auto load_tiles = [&](int s, int kg) {
        #pragma unroll
        for (int u = 0; u < 2; u++) {
            int e = u * 256 + tid;
            int row = e >> 2, cw = e & 3;
            int m = m0 + row;
            int b = m >> 10, rem = m & 1023;
            int oh = rem >> 5, ow = rem & 31;
            int k = kg + cw * 8;
            int di = k >> 10, dj = (k >> 9) & 1, c = k & 511;
            int grow = (b << 12) + (((oh << 1) + di) << 6) + (ow << 1) + dj;
            cp16(sbase + (uint32_t)(s * 2560 + row * 20 + cw * 4) * 4,
                 g_xt + (size_t)grow * 512 + c);
        }
        #pragma unroll
        for (int u = 0; u < 2; u++) {
            int e = u * 256 + tid;
            int row = e >> 2, cw = e & 3;
            cp16(sbase + (uint32_t)(OB + s * 2560 + row * 20 + cw * 4) * 4,
                 g_wsr + (size_t)(n0 + row) * Kfull + kg + cw * 8);
        }
    };

    const int KT = 32;   // 1024 / 32
    load_tiles(0, kz0);
    cp_commit();
    load_tiles(1, kz0 + 32);
    cp_commit();

    for (int kt = 0; kt < KT; kt++) {
        if (kt < KT - 1) { cp_wait<1>(); } else { cp_wait<0>(); }
        __syncthreads();
        if (kt + 2 < KT) {
            load_tiles((kt + 2) % 3, kz0 + (kt + 2) * 32);
            cp_commit();
        }
        const int stage = kt % 3;

        const uint32_t* Ab = smem + stage * 2560;
        const uint32_t* Bb = smem + OB + stage * 2560;
        #pragma unroll
        for (int j = 0; j < 2; j++) {
            uint32_t a[2][4], bf[8][2];
            #pragma unroll
            for (int mt = 0; mt < 2; mt++) {
                int r = wm * 32 + mt * 16 + l2;
                a[mt][0] = Ab[r * 20 + j * 8 + l4];
                a[mt][1] = Ab[(r + 8) * 20 + j * 8 + l4];
                a[mt][2] = Ab[r * 20 + j * 8 + l4 + 4];
                a[mt][3] = Ab[(r + 8) * 20 + j * 8 + l4 + 4];
            }
            #pragma unroll
            for (int nt = 0; nt < 8; nt++) {
                int col = wn * 64 + nt * 8 + l2;
                bf[nt][0] = Bb[col * 20 + j * 8 + l4];
                bf[nt][1] = Bb[col * 20 + j * 8 + l4 + 4];
            }
            #pragma unroll
            for (int mt = 0; mt < 2; mt++)
                #pragma unroll
                for (int nt = 0; nt < 8; nt++)
                    mma16(acc[mt][nt], a[mt], bf[nt]);
        }
        __syncthreads();
    }

    float* dst = (z == 0) ? g_xr : g_xr2;
    #pragma unroll
    for (int mt = 0; mt < 2; mt++) {
        #pragma unroll
        for (int nt = 0; nt < 8; nt++) {
            int r = m0 + wm * 32 + mt * 16 + l2;
            int c = n0 + wn * 64 + nt * 8 + l4 * 2;
            float b0 = 0.0f, b1 = 0.0f;
            if (z == 0) { b0 = bias[c]; b1 = bias[c + 1]; }
            *(float2*)(dst + (size_t)r * 512 + c) =
                make_float2(acc[mt][nt][0] + b0, acc[mt][nt][1] + b1);
            *(float2*)(dst + (size_t)(r + 8) * 512 + c) =
                make_float2(acc[mt][nt][2] + b0, acc[mt][nt][3] + b1);
        }
    }
}

// ---------------------------------------------------------------------------
// Merged Q-projection + conv kernel: blocks [0,256) wide Q-proj,
// [256,512) conv split-K=2. One launch -> one shared wave tail.
// ---------------------------------------------------------------------------
__global__ void __launch_bounds__(256) qconv(
    const float* __restrict__ bq, const float* __restrict__ srb)
{
    extern __shared__ uint32_t smem[];
    int bid = blockIdx.x;
    if (bid < 256) {
        // Q-proj: m0 = (bid>>1)*128, n0 = (bid&1)*256
        wide_body<0>(smem, (bid >> 1) * 128, (bid & 1) * 256, bq, nullptr);
    } else {
        int t = bid - 256;                 // [0,256)
        int xb = t & 3, yb = (t >> 2) & 31, z = t >> 7;
        conv_body(smem, yb * 128, xb * 128, z, srb);
    }
}

// ---------------------------------------------------------------------------
// Out-projection (wide GEMM, MODE 3).
// ---------------------------------------------------------------------------
__global__ void __launch_bounds__(256) outproj(
    const float* __restrict__ bias, float* __restrict__ Cout)
{
    extern __shared__ uint32_t smem[];
    wide_body<3>(smem, (int)blockIdx.y * 128, (int)blockIdx.x * 256, bias, Cout);
}

// ---------------------------------------------------------------------------
// KV projection fp16 GEMM: block 128x128, BK=32, 3-stage ring.
// A=g_xrh, B=g_wkv^T -> g_k / g_v (transposed) (+bias)
// ---------------------------------------------------------------------------
__global__ void __launch_bounds__(256) gemm_kv(const float* __restrict__ bias)
{
    extern __shared__ uint32_t smem[];
    const int OB = 3 * 128 * 20;
    const int Kfull = 512;

    const int tid = threadIdx.x, lane = tid & 31, warp = tid >> 5;
    const int wm = warp >> 1, wn = warp & 1;
    const int l2 = lane >> 2, l4 = lane & 3;
    const int m0 = blockIdx.y * 128, n0 = blockIdx.x * 128;

    const uint32_t sbase = (uint32_t)__cvta_generic_to_shared(smem);

    float acc[2][8][4] = {};

    auto load_tiles = [&](int s, int kg) {
        #pragma unroll
        for (int u = 0; u < 2; u++) {
            int e = u * 256 + tid;
            int row = e >> 2, cw = e & 3;
            cp16(sbase + (uint32_t)(s * 2560 + row * 20 + cw * 4) * 4,
                 g_xrh + (size_t)(m0 + row) * Kfull + kg + cw * 8);
        }
        #pragma unroll
        for (int u = 0; u < 2; u++) {
            int e = u * 256 + tid;
            int row = e >> 2, cw = e & 3;
            cp16(sbase + (uint32_t)(OB + s * 2560 + row * 20 + cw * 4) * 4,
                 g_wkv + (size_t)(n0 + row) * Kfull + kg + cw * 8);
        }
    };

    const int KT = Kfull >> 5;
    load_tiles(0, 0);
    cp_commit();
    load_tiles(1, 32);
    cp_commit();

    for (int kt = 0; kt < KT; kt++) {
        if (kt < KT - 1) { cp_wait<1>(); } else { cp_wait<0>(); }
        __syncthreads();
        if (kt + 2 < KT) {
            load_tiles((kt + 2) % 3, (kt + 2) * 32);
            cp_commit();
        }
        const int stage = kt % 3;

        const uint32_t* Ab = smem + stage * 2560;
        const uint32_t* Bb = smem + OB + stage * 2560;
        #pragma unroll
        for (int j = 0; j < 2; j++) {
            uint32_t a[2][4], bf[8][2];
            #pragma unroll
            for (int mt = 0; mt < 2; mt++) {
                int r = wm * 32 + mt * 16 + l2;
                a[mt][0] = Ab[r * 20 + j * 8 + l4];
                a[mt][1] = Ab[(r + 8) * 20 + j * 8 + l4];
                a[mt][2] = Ab[r * 20 + j * 8 + l4 + 4];
                a[mt][3] = Ab[(r + 8) * 20 + j * 8 + l4 + 4];
            }
            #pragma unroll
            for (int nt = 0; nt < 8; nt++) {
                int col = wn * 64 + nt * 8 + l2;
                bf[nt][0] = Bb[col * 20 + j * 8 + l4];
                bf[nt][1] = Bb[col * 20 + j * 8 + l4 + 4];
            }
            #pragma unroll
            for (int mt = 0; mt < 2; mt++)
                #pragma unroll
                for (int nt = 0; nt < 8; nt++)
                    mma16(acc[mt][nt], a[mt], bf[nt]);
        }
        __syncthreads();
    }

    #pragma unroll
    for (int mt = 0; mt < 2; mt++) {
        #pragma unroll
        for (int nt = 0; nt < 8; nt++) {
            int r = m0 + wm * 32 + mt * 16 + l2;
            int c = n0 + wn * 64 + nt * 8 + l4 * 2;
            float b0 = bias[c], b1 = bias[c + 1];
            float v00 = acc[mt][nt][0] + b0, v01 = acc[mt][nt][1] + b1;
            float v10 = acc[mt][nt][2] + b0, v11 = acc[mt][nt][3] + b1;
            int cc = c & 511, h = cc >> 6, d = cc & 63;
            int b_ = r >> 10, mi = r & 1023;
            size_t bhO = (size_t)(b_ * 8 + h) * 65536;
            if (c < 512) {
                *(uint32_t*)(g_k + bhO + (size_t)mi * 64 + d) = pack2(v00, v01);
                *(uint32_t*)(g_k + bhO + (size_t)(mi + 8) * 64 + d) = pack2(v10, v11);
            } else {
                g_v[bhO + (size_t)d * 1024 + mi]           = __float2half_rn(v00);
                g_v[bhO + (size_t)(d + 1) * 1024 + mi]     = __float2half_rn(v01);
                g_v[bhO + (size_t)d * 1024 + mi + 8]       = __float2half_rn(v10);
                g_v[bhO + (size_t)(d + 1) * 1024 + mi + 8] = __float2half_rn(v11);
            }
        }
    }
}

// ---------------------------------------------------------------------------
// LayerNorm: sums 2 split-K partials, writes g_xrh (half). eps=1e-3.
// ---------------------------------------------------------------------------
__global__ void __launch_bounds__(128) ln_kernel(
    const float* __restrict__ gamma, const float* __restrict__ beta)
{
    int row = blockIdx.x;
    int t = threadIdx.x;
    size_t off = (size_t)row * 512 + t * 4;

    float4 v  = *(const float4*)(g_xr + off);
    float4 v2 = *(const float4*)(g_xr2 + off);
    v.x += v2.x; v.y += v2.y; v.z += v2.z; v.w += v2.w;

    float s  = v.x + v.y + v.z + v.w;
    float s2 = v.x * v.x + v.y * v.y + v.z * v.z + v.w * v.w;

    #pragma unroll
    for (int o = 16; o > 0; o >>= 1) {
        s  += __shfl_xor_sync(0xffffffffu, s, o);
        s2 += __shfl_xor_sync(0xffffffffu, s2, o);
    }
    __shared__ float red[2][4];
    int w = t >> 5;
    if ((t & 31) == 0) { red[0][w] = s; red[1][w] = s2; }
    __syncthreads();
    s  = red[0][0] + red[0][1] + red[0][2] + red[0][3];
    s2 = red[1][0] + red[1][1] + red[1][2] + red[1][3];

    float mu  = s * (1.0f / 512.0f);
    float var = s2 * (1.0f / 512.0f) - mu * mu;
    float inv = rsqrtf(var + 1e-3f);

    float4 g  = *(const float4*)(gamma + t * 4);
    float4 be = *(const float4*)(beta + t * 4);
    uint2 o;
    o.x = pack2((v.x - mu) * inv * g.x + be.x, (v.y - mu) * inv * g.y + be.y);
    o.y = pack2((v.z - mu) * inv * g.z + be.z, (v.w - mu) * inv * g.w + be.w);
    *(uint2*)(g_xrh + off) = o;
}

// ---------------------------------------------------------------------------
// Flash attention fp16: 128 threads / 4 warps, each warp owns 32 q rows
// (two 16-row fragment groups) -> K/V fragments reused across both groups.
// BQ=128, BKV=64, log2-domain ex2 softmax, 3-stage cp.async ring.
// smem u32: K[3][64][36] | V[3][64][36] = 55296 B.
// ---------------------------------------------------------------------------
__global__ void __launch_bounds__(128) attn_h()
{
    extern __shared__ uint32_t sm[];
    const int VOFF = 3 * 64 * 36;

    const int tid = threadIdx.x, lane = tid & 31, warp = tid >> 5;  // warp 0..3
    const int l2 = lane >> 2, l4 = lane & 3;
    const int bh = blockIdx.y, b = bh >> 3, h = bh & 7;
    const int q0 = blockIdx.x * 128;

    const __half* Kg = g_k + (size_t)bh * 65536;
    const __half* Vg = g_v + (size_t)bh * 65536;  // [d][m]

    const uint32_t sbase = (uint32_t)__cvta_generic_to_shared(sm);

    auto loadKV = [&](int s, int kv0) {
        #pragma unroll
        for (int u = 0; u < 4; u++) {
            int e = u * 128 + tid;
            int r = e >> 3, cw = e & 7;
            cp16(sbase + (uint32_t)(s * 2304 + r * 36 + cw * 4) * 4,
                 Kg + (size_t)(kv0 + r) * 64 + cw * 8);
            cp16(sbase + (uint32_t)(VOFF + s * 2304 + r * 36 + cw * 4) * 4,
                 Vg + (size_t)r * 1024 + kv0 + cw * 8);
        }
    };

    loadKV(0, 0);
    cp_commit();
    loadKV(1, 64);
    cp_commit();

    // Q fragments for two 16-row groups: tiles 2*warp, 2*warp+1
    uint32_t qf[2][4][4];
    {
        const uint4* Qf = (const uint4*)g_q;
        #pragma unroll
        for (int g = 0; g < 2; g++) {
            size_t base = ((size_t)(bh * 256 + blockIdx.x * 8 + warp * 2 + g) * 4) * 32;
            #pragma unroll
            for (int j = 0; j < 4; j++) {
                uint4 v = Qf[base + j * 32 + lane];
                qf[g][j][0] = v.x; qf[g][j][1] = v.y;
                qf[g][j][2] = v.z; qf[g][j][3] = v.w;
            }
        }
    }

    float oacc[2][8][4] = {};
    float lac[2][2] = {};

    for (int kc = 0; kc < 16; kc++) {
        if (kc < 15) { cp_wait<1>(); } else { cp_wait<0>(); }
        __syncthreads();
        if (kc + 2 < 16) {
            loadKV((kc + 2) % 3, (kc + 2) * 64);
            cp_commit();
        }
        const int stage = kc % 3;

        // S = Q K^T (log2 domain); K fragments shared across both row groups
        float sacc[2][8][4] = {};
        const uint32_t* Kb = sm + stage * 2304;
        #pragma unroll
        for (int j = 0; j < 4; j++) {
            uint32_t bfr[8][2];
            #pragma unroll
            for (int nt = 0; nt < 8; nt++) {
                int kvi = nt * 8 + l2;
                bfr[nt][0] = Kb[kvi * 36 + j * 8 + l4];
                bfr[nt][1] = Kb[kvi * 36 + j * 8 + l4 + 4];
            }
            #pragma unroll
            for (int g = 0; g < 2; g++)
                #pragma unroll
                for (int nt = 0; nt < 8; nt++)
                    mma16(sacc[g][nt], qf[g][j], bfr[nt]);
        }

        // O += P V ; V fragments shared across both row groups
        const uint32_t* Vb = sm + VOFF + stage * 2304;
        #pragma unroll
        for (int j = 0; j < 4; j++) {
            uint32_t vfr[8][2];
            #pragma unroll
            for (int nt = 0; nt < 8; nt++) {
                int d = nt * 8 + l2;
                vfr[nt][0] = Vb[d * 36 + j * 8 + l4];
                vfr[nt][1] = Vb[d * 36 + j * 8 + l4 + 4];
            }
            #pragma unroll
            for (int g = 0; g < 2; g++) {
                uint32_t a[4];
                a[0] = h2ex2(pack2(sacc[g][2 * j][0],     sacc[g][2 * j][1]));
                a[1] = h2ex2(pack2(sacc[g][2 * j][2],     sacc[g][2 * j][3]));
                a[2] = h2ex2(pack2(sacc[g][2 * j + 1][0], sacc[g][2 * j + 1][1]));
                a[3] = h2ex2(pack2(sacc[g][2 * j + 1][2], sacc[g][2 * j + 1][3]));
                float2 f0 = h2f2(a[0]), f1 = h2f2(a[1]);
                float2 f2 = h2f2(a[2]), f3 = h2f2(a[3]);
                lac[g][0] += f0.x + f0.y + f2.x + f2.y;
                lac[g][1] += f1.x + f1.y + f3.x + f3.y;
                #pragma unroll
                for (int nt = 0; nt < 8; nt++)
                    mma16(oacc[g][nt], a, vfr[nt]);
            }
        }
    }

    // reduce l across quads, normalize, write half
    #pragma unroll
    for (int g = 0; g < 2; g++) {
        float l0 = lac[g][0], l1 = lac[g][1];
        l0 += __shfl_xor_sync(0xffffffffu, l0, 1);
        l0 += __shfl_xor_sync(0xffffffffu, l0, 2);
        l1 += __shfl_xor_sync(0xffffffffu, l1, 1);
        l1 += __shfl_xor_sync(0xffffffffu, l1, 2);
        float i0 = 1.0f / l0, i1 = 1.0f / l1;
        int n = q0 + warp * 32 + g * 16 + l2;
        #pragma unroll
        for (int nt = 0; nt < 8; nt++) {
            int d = nt * 8 + l4 * 2;
            *(uint32_t*)(g_att + ((size_t)(b * 4096 + n) * 512 + h * 64 + d)) =
                pack2(oacc[g][nt][0] * i0, oacc[g][nt][1] * i0);
            *(uint32_t*)(g_att + ((size_t)(b * 4096 + n + 8) * 512 + h * 64 + d)) =
                pack2(oacc[g][nt][2] * i1, oacc[g][nt][3] * i1);
        }
    }
}

// ---------------------------------------------------------------------------
// Launcher
// ---------------------------------------------------------------------------
extern "C" void kernel_launch(void* const* d_in, const int* in_sizes, int n_in,
                              void* d_out, int out_size)
{
    const float *x = 0, *Wq = 0, *bq = 0, *Wkv = 0, *bkv = 0, *Wp = 0, *bp = 0;
    const float *srk = 0, *srb = 0, *gma = 0, *bta = 0;
    const float* s512[5] = {0, 0, 0, 0, 0};
    const float* s256k[2] = {0, 0};
    int n512 = 0, nbig = 0;

    for (int i = 0; i < n_in; i++) {
        int sz = in_sizes[i];
        const float* p = (const float*)d_in[i];
        if (sz == 8388608 && !x) x = p;
        else if (sz == 262144 && nbig < 2) s256k[nbig++] = p;
        else if (sz == 524288) Wkv = p;
        else if (sz == 1048576) srk = p;
        else if (sz == 1024) bkv = p;
        else if (sz == 512 && n512 < 5) s512[n512++] = p;
    }
    Wq = s256k[0]; Wp = s256k[1];
    bq = s512[0]; bp = s512[1]; srb = s512[2]; gma = s512[3]; bta = s512[4];
    float* out = (float*)d_out;

    const int wide_smem = (3 * 128 * 20 + 3 * 256 * 20) * 4;  // 92160
    const int nar_smem  = (3 * 128 * 20 + 3 * 128 * 20) * 4;  // 61440
    const int attn_smem = 6 * 64 * 36 * 4;                    // 55296
    cudaFuncSetAttribute(qconv,   cudaFuncAttributeMaxDynamicSharedMemorySize, wide_smem);
    cudaFuncSetAttribute(outproj, cudaFuncAttributeMaxDynamicSharedMemorySize, wide_smem);
    cudaFuncSetAttribute(gemm_kv, cudaFuncAttributeMaxDynamicSharedMemorySize, nar_smem);
    cudaFuncSetAttribute(attn_h,  cudaFuncAttributeMaxDynamicSharedMemorySize, attn_smem);

    // merged pre-pass (x convert + weight transpose)
    prepass<<<10240, 256>>>((const float4*)x, Wq, Wkv, Wp, srk);
    // merged Q projection + SR conv (split-K=2), one wave tail
    qconv<<<512, 256, wide_smem>>>(bq, srb);
    // LayerNorm (sums 2 partials) -> g_xrh
    ln_kernel<<<4096, 128>>>(gma, bta);
    // KV projection -> g_k, g_v (V transposed)
    gemm_kv<<<dim3(8, 32), 256, nar_smem>>>(bkv);
    // attention (128 threads, 4 warps x 32 rows)
    attn_h<<<dim3(32, 32), 128, attn_smem>>>();
    // output projection -> d_out fp32
    outproj<<<dim3(2, 128), 256, wide_smem>>>(bp, out);
    (void)out_size;
}

// round 13
// speedup vs baseline: 1.0204x; 1.0204x over previous
#include <cuda_runtime.h>
#include <cuda_fp16.h>
#include <math.h>
#include <stdint.h>

// ---------------------------------------------------------------------------
// EfficientSelfAttention (PVT SRA): B=4, N=4096 (64x64), C=512, heads=8,
// head_dim=64, SR=2 -> N_kv=1024.  fp16 m16n8k16 mma.sync (fp32 accum).
// Round 13: round-11 structure (separate launches) with ALL four GEMMs on
// the wide 128x256 tile (1.0 LDS/mma): Q-proj, conv (split-K=2), KV, out.
// ---------------------------------------------------------------------------

__device__ __half  g_xt[8388608];   // x as half [16384][512]
__device__ float   g_xr[2097152];   // conv partial z=0 (fp32, +bias)
__device__ float   g_xr2[2097152];  // conv partial z=1
__device__ __half  g_xrh[2097152];  // LN output half
__device__ __half  g_k[2097152];    // [bh][m][d]
__device__ __half  g_v[2097152];    // TRANSPOSED: [bh][d][m]
__device__ __half  g_att[8388608];  // [b,n, h*64+d]
__device__ uint32_t g_q[4194304];   // Q in fp16 A-fragment order (log2-scaled)
__device__ __half  g_wq[262144];    // W^T [N][K]
__device__ __half  g_wkv[524288];
__device__ __half  g_wp[262144];
__device__ __half  g_wsr[1048576];

#define QSCALE 0.18033688011112042f   // 0.125 * log2(e)

__device__ __forceinline__ uint32_t pack2(float a, float b) {
    __half2 h = __floats2half2_rn(a, b);
    return *(uint32_t*)&h;
}
__device__ __forceinline__ uint32_t h2ex2(uint32_t x) {
    uint32_t r;
    asm("ex2.approx.f16x2 %0, %1;" : "=r"(r) : "r"(x));
    return r;
}
__device__ __forceinline__ float2 h2f2(uint32_t x) {
    __half2 h = *(__half2*)&x;
    return __half22float2(h);
}

__device__ __forceinline__ void mma16(float* c, const uint32_t* a, const uint32_t* b) {
    asm("mma.sync.aligned.m16n8k16.row.col.f32.f16.f16.f32 "
        "{%0,%1,%2,%3}, {%4,%5,%6,%7}, {%8,%9}, {%0,%1,%2,%3};"
        : "+f"(c[0]), "+f"(c[1]), "+f"(c[2]), "+f"(c[3])
        : "r"(a[0]), "r"(a[1]), "r"(a[2]), "r"(a[3]), "r"(b[0]), "r"(b[1]));
}

__device__ __forceinline__ void cp16(uint32_t dst, const void* src) {
    asm volatile("cp.async.cg.shared.global [%0], [%1], 16;" :: "r"(dst), "l"(src));
}
__device__ __forceinline__ void cp_commit() {
    asm volatile("cp.async.commit_group;");
}
template <int N>
__device__ __forceinline__ void cp_wait() {
    asm volatile("cp.async.wait_group %0;" :: "n"(N));
}

// ---------------------------------------------------------------------------
// Merged pre-pass: blocks [0,8192) convert x -> half; [8192,10240) transpose
// weights fp32 [K][N] -> half [N][K].
// ---------------------------------------------------------------------------
__global__ void __launch_bounds__(256) prepass(
    const float4* __restrict__ x,
    const float* __restrict__ wq, const float* __restrict__ wkv,
    const float* __restrict__ wp, const float* __restrict__ wsr)
{
    __shared__ float tile[32][33];
    if (blockIdx.x < 8192) {
        int i = blockIdx.x * 256 + threadIdx.x;
        float4 v = x[i];
        uint2 o;
        o.x = pack2(v.x, v.y);
        o.y = pack2(v.z, v.w);
        *(uint2*)(g_xt + (size_t)i * 4) = o;
        return;
    }
    int t = blockIdx.x - 8192;
    const float* src; __half* dst; int K, N, tk, tn;
    if (t < 256)       { src = wq;  dst = g_wq;  K = 512;  N = 512;  tk = t >> 4; tn = t & 15; }
    else if (t < 768)  { t -= 256;  src = wkv; dst = g_wkv; K = 512;  N = 1024; tk = t >> 5; tn = t & 31; }
    else if (t < 1024) { t -= 768;  src = wp;  dst = g_wp;  K = 512;  N = 512;  tk = t >> 4; tn = t & 15; }
    else               { t -= 1024; src = wsr; dst = g_wsr; K = 2048; N = 512;  tk = t >> 4; tn = t & 15; }

    int tx = threadIdx.x & 31, ty = threadIdx.x >> 5;
    int k0 = tk * 32, n0 = tn * 32;
    #pragma unroll
    for (int i = 0; i < 4; i++)
        tile[tx][ty + 8 * i] = src[(size_t)(k0 + ty + 8 * i) * N + n0 + tx];
    __syncthreads();
    #pragma unroll
    for (int i = 0; i < 4; i++) {
        int row = ty + 8 * i;
        dst[(size_t)(n0 + row) * K + k0 + tx] = __float2half_rn(tile[row][tx]);
    }
}

// ---------------------------------------------------------------------------
// Wide fp16 GEMM: tile 128x256, BK=32, 3-stage cp.async ring, 8 warps (2x4),
// warp tile 64x64 (1.0 LDS per mma).
// MODE 0: A=g_xt,  B=g_wq^T  -> g_q fragment-order (*QSCALE, +bias)
// MODE 1: A=g_xt (conv patch gather, split-K z), B=g_wsr^T -> g_xr/g_xr2
// MODE 2: A=g_xrh, B=g_wkv^T -> g_k / g_v (transposed) (+bias)
// MODE 3: A=g_att, B=g_wp^T  -> Cout fp32 (+bias)
// smem u32: A[3][128][20] @0 | B[3][256][20] @7680  (92160 B)
// ---------------------------------------------------------------------------
template <int MODE>
__global__ void __launch_bounds__(256) gemm_wide(
    const float* __restrict__ bias, float* __restrict__ Cout)
{
    extern __shared__ uint32_t smem[];
    const int OB = 3 * 128 * 20;  // 7680

    const int tid = threadIdx.x, lane = tid & 31, warp = tid >> 5;
    const int wm = warp >> 2, wn = warp & 3;
    const int l2 = lane >> 2, l4 = lane & 3;
    const int m0 = blockIdx.y * 128, n0 = blockIdx.x * 256;

    const int BK   = (MODE == 1) ? 2048 : 512;   // B row stride (halves)
    const int kz0  = (MODE == 1) ? (int)blockIdx.z * 1024 : 0;
    const int KT   = (MODE == 1) ? 32 : 16;

    const __half* Ap = (MODE == 0 || MODE == 1) ? g_xt
                      : (MODE == 2) ? g_xrh : g_att;
    const __half* Bp = (MODE == 0) ? g_wq : (MODE == 1) ? g_wsr
                      : (MODE == 2) ? g_wkv : g_wp;

    const uint32_t sbase = (uint32_t)__cvta_generic_to_shared(smem);

    float acc[4][8][4] = {};

    auto load_tiles = [&](int s, int kg) {
        #pragma unroll
        for (int u = 0; u < 2; u++) {           // A: 128 rows x 4 cp16
            int e = u * 256 + tid;
            int row = e >> 2, cw = e & 3;
            const __half* src;
            if (MODE == 1) {
                int m = m0 + row;
                int b = m >> 10, rem = m & 1023;
                int oh = rem >> 5, ow = rem & 31;
                int k = kg + cw * 8;
                int di = k >> 10, dj = (k >> 9) & 1, c = k & 511;
                int grow = (b << 12) + (((oh << 1) + di) << 6) + (ow << 1) + dj;
                src = g_xt + (size_t)grow * 512 + c;
            } else {
                src = Ap + (size_t)(m0 + row) * 512 + kg + cw * 8;
            }
            cp16(sbase + (uint32_t)(s * 2560 + row * 20 + cw * 4) * 4, src);
        }
        #pragma unroll
        for (int u = 0; u < 4; u++) {           // B: 256 rows x 4 cp16
            int e = u * 256 + tid;
            int row = e >> 2, cw = e & 3;
            cp16(sbase + (uint32_t)(OB + s * 5120 + row * 20 + cw * 4) * 4,
                 Bp + (size_t)(n0 + row) * BK + kg + cw * 8);
        }
    };

    load_tiles(0, kz0);
    cp_commit();
    load_tiles(1, kz0 + 32);
    cp_commit();

    for (int kt = 0; kt < KT; kt++) {
        if (kt < KT - 1) { cp_wait<1>(); } else { cp_wait<0>(); }
        __syncthreads();
        if (kt + 2 < KT) {
            load_tiles((kt + 2) % 3, kz0 + (kt + 2) * 32);
            cp_commit();
        }
        const int stage = kt % 3;

        const uint32_t* Ab = smem + stage * 2560;
        const uint32_t* Bb = smem + OB + stage * 5120;
        #pragma unroll
        for (int j = 0; j < 2; j++) {
            uint32_t a[4][4], bf[8][2];
            #pragma unroll
            for (int mt = 0; mt < 4; mt++) {
                int r = wm * 64 + mt * 16 + l2;
                a[mt][0] = Ab[r * 20 + j * 8 + l4];
                a[mt][1] = Ab[(r + 8) * 20 + j * 8 + l4];
                a[mt][2] = Ab[r * 20 + j * 8 + l4 + 4];
                a[mt][3] = Ab[(r + 8) * 20 + j * 8 + l4 + 4];
            }
            #pragma unroll
            for (int nt = 0; nt < 8; nt++) {
                int col = wn * 64 + nt * 8 + l2;
                bf[nt][0] = Bb[col * 20 + j * 8 + l4];
                bf[nt][1] = Bb[col * 20 + j * 8 + l4 + 4];
            }
            #pragma unroll
            for (int mt = 0; mt < 4; mt++)
                #pragma unroll
                for (int nt = 0; nt < 8; nt++)
                    mma16(acc[mt][nt], a[mt], bf[nt]);
        }
        __syncthreads();
    }

    // epilogue
    #pragma unroll
    for (int mt = 0; mt < 4; mt++) {
        #pragma unroll
        for (int nt = 0; nt < 8; nt++) {
            int r = m0 + wm * 64 + mt * 16 + l2;
            int c = n0 + wn * 64 + nt * 8 + l4 * 2;
            if (MODE == 1) {
                float b0 = 0.0f, b1 = 0.0f;
                if (blockIdx.z == 0) { b0 = bias[c]; b1 = bias[c + 1]; }
                float* dst = (blockIdx.z == 0) ? g_xr : g_xr2;
                *(float2*)(dst + (size_t)r * 512 + c) =
                    make_float2(acc[mt][nt][0] + b0, acc[mt][nt][1] + b1);
                *(float2*)(dst + (size_t)(r + 8) * 512 + c) =
                    make_float2(acc[mt][nt][2] + b0, acc[mt][nt][3] + b1);
                continue;
            }
            float b0 = bias[c], b1 = bias[c + 1];
            float v00 = acc[mt][nt][0] + b0, v01 = acc[mt][nt][1] + b1;
            float v10 = acc[mt][nt][2] + b0, v11 = acc[mt][nt][3] + b1;
            if (MODE == 0) {
                int b_ = r >> 12, nq = r & 4095;
                int h = c >> 6, d = c & 63;
                int bh = b_ * 8 + h, ntile = nq >> 4;
                int j = d >> 4, wsel = (d >> 3) & 1;
                size_t base = (((size_t)(bh * 256 + ntile) * 4 + j) * 32 + lane) * 4 + wsel * 2;
                g_q[base]     = pack2(v00 * QSCALE, v01 * QSCALE);
                g_q[base + 1] = pack2(v10 * QSCALE, v11 * QSCALE);
            } else if (MODE == 2) {
                int cc = c & 511, h = cc >> 6, d = cc & 63;
                int b_ = r >> 10, mi = r & 1023;
                size_t bhO = (size_t)(b_ * 8 + h) * 65536;
                if (c < 512) {
                    *(uint32_t*)(g_k + bhO + (size_t)mi * 64 + d) = pack2(v00, v01);
                    *(uint32_t*)(g_k + bhO + (size_t)(mi + 8) * 64 + d) = pack2(v10, v11);
                } else {
                    g_v[bhO + (size_t)d * 1024 + mi]           = __float2half_rn(v00);
                    g_v[bhO + (size_t)(d + 1) * 1024 + mi]     = __float2half_rn(v01);
                    g_v[bhO + (size_t)d * 1024 + mi + 8]       = __float2half_rn(v10);
                    g_v[bhO + (size_t)(d + 1) * 1024 + mi + 8] = __float2half_rn(v11);
                }
            } else {
                *(float2*)(Cout + (size_t)r * 512 + c) = make_float2(v00, v01);
                *(float2*)(Cout + (size_t)(r + 8) * 512 + c) = make_float2(v10, v11);
            }
        }
    }
}

// ---------------------------------------------------------------------------
// LayerNorm: sums 2 split-K partials, writes g_xrh (half). eps=1e-3.
// ---------------------------------------------------------------------------
__global__ void __launch_bounds__(128) ln_kernel(
    const float* __restrict__ gamma, const float* __restrict__ beta)
{
    int row = blockIdx.x;
    int t = threadIdx.x;
    size_t off = (size_t)row * 512 + t * 4;

    float4 v  = *(const float4*)(g_xr + off);
    float4 v2 = *(const float4*)(g_xr2 + off);
    v.x += v2.x; v.y += v2.y; v.z += v2.z; v.w += v2.w;

    float s  = v.x + v.y + v.z + v.w;
    float s2 = v.x * v.x + v.y * v.y + v.z * v.z + v.w * v.w;

    #pragma unroll
    for (int o = 16; o > 0; o >>= 1) {
        s  += __shfl_xor_sync(0xffffffffu, s, o);
        s2 += __shfl_xor_sync(0xffffffffu, s2, o);
    }
    __shared__ float red[2][4];
    int w = t >> 5;
    if ((t & 31) == 0) { red[0][w] = s; red[1][w] = s2; }
    __syncthreads();
    s  = red[0][0] + red[0][1] + red[0][2] + red[0][3];
    s2 = red[1][0] + red[1][1] + red[1][2] + red[1][3];

    float mu  = s * (1.0f / 512.0f);
    float var = s2 * (1.0f / 512.0f) - mu * mu;
    float inv = rsqrtf(var + 1e-3f);

    float4 g  = *(const float4*)(gamma + t * 4);
    float4 be = *(const float4*)(beta + t * 4);
    uint2 o;
    o.x = pack2((v.x - mu) * inv * g.x + be.x, (v.y - mu) * inv * g.y + be.y);
    o.y = pack2((v.z - mu) * inv * g.z + be.z, (v.w - mu) * inv * g.w + be.w);
    *(uint2*)(g_xrh + off) = o;
}

// ---------------------------------------------------------------------------
// Flash attention fp16: 128 threads / 4 warps, each warp owns 32 q rows
// (two 16-row fragment groups) -> K/V fragments reused across both groups.
// BQ=128, BKV=64, log2-domain ex2 softmax, 3-stage cp.async ring.
// smem u32: K[3][64][36] | V[3][64][36] = 55296 B.
// ---------------------------------------------------------------------------
__global__ void __launch_bounds__(128) attn_h()
{
    extern __shared__ uint32_t sm[];
    const int VOFF = 3 * 64 * 36;

    const int tid = threadIdx.x, lane = tid & 31, warp = tid >> 5;  // warp 0..3
    const int l2 = lane >> 2, l4 = lane & 3;
    const int bh = blockIdx.y, b = bh >> 3, h = bh & 7;
    const int q0 = blockIdx.x * 128;

    const __half* Kg = g_k + (size_t)bh * 65536;
    const __half* Vg = g_v + (size_t)bh * 65536;  // [d][m]

    const uint32_t sbase = (uint32_t)__cvta_generic_to_shared(sm);

    auto loadKV = [&](int s, int kv0) {
        #pragma unroll
        for (int u = 0; u < 4; u++) {
            int e = u * 128 + tid;
            int r = e >> 3, cw = e & 7;
            cp16(sbase + (uint32_t)(s * 2304 + r * 36 + cw * 4) * 4,
                 Kg + (size_t)(kv0 + r) * 64 + cw * 8);
            cp16(sbase + (uint32_t)(VOFF + s * 2304 + r * 36 + cw * 4) * 4,
                 Vg + (size_t)r * 1024 + kv0 + cw * 8);
        }
    };

    loadKV(0, 0);
    cp_commit();
    loadKV(1, 64);
    cp_commit();

    // Q fragments for two 16-row groups: tiles 2*warp, 2*warp+1
    uint32_t qf[2][4][4];
    {
        const uint4* Qf = (const uint4*)g_q;
        #pragma unroll
        for (int g = 0; g < 2; g++) {
            size_t base = ((size_t)(bh * 256 + blockIdx.x * 8 + warp * 2 + g) * 4) * 32;
            #pragma unroll
            for (int j = 0; j < 4; j++) {
                uint4 v = Qf[base + j * 32 + lane];
                qf[g][j][0] = v.x; qf[g][j][1] = v.y;
                qf[g][j][2] = v.z; qf[g][j][3] = v.w;
            }
        }
    }

    float oacc[2][8][4] = {};
    float lac[2][2] = {};

    for (int kc = 0; kc < 16; kc++) {
        if (kc < 15) { cp_wait<1>(); } else { cp_wait<0>(); }
        __syncthreads();
        if (kc + 2 < 16) {
            loadKV((kc + 2) % 3, (kc + 2) * 64);
            cp_commit();
        }
        const int stage = kc % 3;

        // S = Q K^T (log2 domain); K fragments shared across both row groups
        float sacc[2][8][4] = {};
        const uint32_t* Kb = sm + stage * 2304;
        #pragma unroll
        for (int j = 0; j < 4; j++) {
            uint32_t bfr[8][2];
            #pragma unroll
            for (int nt = 0; nt < 8; nt++) {
                int kvi = nt * 8 + l2;
                bfr[nt][0] = Kb[kvi * 36 + j * 8 + l4];
                bfr[nt][1] = Kb[kvi * 36 + j * 8 + l4 + 4];
            }
            #pragma unroll
            for (int g = 0; g < 2; g++)
                #pragma unroll
                for (int nt = 0; nt < 8; nt++)
                    mma16(sacc[g][nt], qf[g][j], bfr[nt]);
        }

        // O += P V ; V fragments shared across both row groups
        const uint32_t* Vb = sm + VOFF + stage * 2304;
        #pragma unroll
        for (int j = 0; j < 4; j++) {
            uint32_t vfr[8][2];
            #pragma unroll
            for (int nt = 0; nt < 8; nt++) {
                int d = nt * 8 + l2;
                vfr[nt][0] = Vb[d * 36 + j * 8 + l4];
                vfr[nt][1] = Vb[d * 36 + j * 8 + l4 + 4];
            }
            #pragma unroll
            for (int g = 0; g < 2; g++) {
                uint32_t a[4];
                a[0] = h2ex2(pack2(sacc[g][2 * j][0],     sacc[g][2 * j][1]));
                a[1] = h2ex2(pack2(sacc[g][2 * j][2],     sacc[g][2 * j][3]));
                a[2] = h2ex2(pack2(sacc[g][2 * j + 1][0], sacc[g][2 * j + 1][1]));
                a[3] = h2ex2(pack2(sacc[g][2 * j + 1][2], sacc[g][2 * j + 1][3]));
                float2 f0 = h2f2(a[0]), f1 = h2f2(a[1]);
                float2 f2 = h2f2(a[2]), f3 = h2f2(a[3]);
                lac[g][0] += f0.x + f0.y + f2.x + f2.y;
                lac[g][1] += f1.x + f1.y + f3.x + f3.y;
                #pragma unroll
                for (int nt = 0; nt < 8; nt++)
                    mma16(oacc[g][nt], a, vfr[nt]);
            }
        }
    }

    // reduce l across quads, normalize, write half
    #pragma unroll
    for (int g = 0; g < 2; g++) {
        float l0 = lac[g][0], l1 = lac[g][1];
        l0 += __shfl_xor_sync(0xffffffffu, l0, 1);
        l0 += __shfl_xor_sync(0xffffffffu, l0, 2);
        l1 += __shfl_xor_sync(0xffffffffu, l1, 1);
        l1 += __shfl_xor_sync(0xffffffffu, l1, 2);
        float i0 = 1.0f / l0, i1 = 1.0f / l1;
        int n = q0 + warp * 32 + g * 16 + l2;
        #pragma unroll
        for (int nt = 0; nt < 8; nt++) {
            int d = nt * 8 + l4 * 2;
            *(uint32_t*)(g_att + ((size_t)(b * 4096 + n) * 512 + h * 64 + d)) =
                pack2(oacc[g][nt][0] * i0, oacc[g][nt][1] * i0);
            *(uint32_t*)(g_att + ((size_t)(b * 4096 + n + 8) * 512 + h * 64 + d)) =
                pack2(oacc[g][nt][2] * i1, oacc[g][nt][3] * i1);
        }
    }
}

// ---------------------------------------------------------------------------
// Launcher
// ---------------------------------------------------------------------------
extern "C" void kernel_launch(void* const* d_in, const int* in_sizes, int n_in,
                              void* d_out, int out_size)
{
    const float *x = 0, *Wq = 0, *bq = 0, *Wkv = 0, *bkv = 0, *Wp = 0, *bp = 0;
    const float *srk = 0, *srb = 0, *gma = 0, *bta = 0;
    const float* s512[5] = {0, 0, 0, 0, 0};
    const float* s256k[2] = {0, 0};
    int n512 = 0, nbig = 0;

    for (int i = 0; i < n_in; i++) {
        int sz = in_sizes[i];
        const float* p = (const float*)d_in[i];
        if (sz == 8388608 && !x) x = p;
        else if (sz == 262144 && nbig < 2) s256k[nbig++] = p;
        else if (sz == 524288) Wkv = p;
        else if (sz == 1048576) srk = p;
        else if (sz == 1024) bkv = p;
        else if (sz == 512 && n512 < 5) s512[n512++] = p;
    }
    Wq = s256k[0]; Wp = s256k[1];
    bq = s512[0]; bp = s512[1]; srb = s512[2]; gma = s512[3]; bta = s512[4];
    float* out = (float*)d_out;

    const int wide_smem = (3 * 128 * 20 + 3 * 256 * 20) * 4;  // 92160
    const int attn_smem = 6 * 64 * 36 * 4;                    // 55296
    cudaFuncSetAttribute(gemm_wide<0>, cudaFuncAttributeMaxDynamicSharedMemorySize, wide_smem);
    cudaFuncSetAttribute(gemm_wide<1>, cudaFuncAttributeMaxDynamicSharedMemorySize, wide_smem);
    cudaFuncSetAttribute(gemm_wide<2>, cudaFuncAttributeMaxDynamicSharedMemorySize, wide_smem);
    cudaFuncSetAttribute(gemm_wide<3>, cudaFuncAttributeMaxDynamicSharedMemorySize, wide_smem);
    cudaFuncSetAttribute(attn_h,  cudaFuncAttributeMaxDynamicSharedMemorySize, attn_smem);

    // merged pre-pass (x convert + weight transpose)
    prepass<<<10240, 256>>>((const float4*)x, Wq, Wkv, Wp, srk);
    // Q projection -> fragment-order g_q (log2 scale): [16384,512]@[512,512]
    gemm_wide<0><<<dim3(2, 128), 256, wide_smem>>>(bq, nullptr);
    // SR conv as patch GEMM, wide tile, split-K=2: [4096,2048]@[2048,512]
    gemm_wide<1><<<dim3(2, 32, 2), 256, wide_smem>>>(srb, nullptr);
    // LayerNorm (sums 2 partials) -> g_xrh
    ln_kernel<<<4096, 128>>>(gma, bta);
    // KV projection wide: [4096,512]@[512,1024] -> g_k, g_v (V transposed)
    gemm_wide<2><<<dim3(4, 32), 256, wide_smem>>>(bkv, nullptr);
    // attention (128 threads, 4 warps x 32 rows)
    attn_h<<<dim3(32, 32), 128, attn_smem>>>();
    // output projection -> d_out fp32
    gemm_wide<3><<<dim3(2, 128), 256, wide_smem>>>(bp, out);
    (void)out_size;
}

// round 14
// speedup vs baseline: 1.0876x; 1.0658x over previous
#include <cuda_runtime.h>
#include <cuda_fp16.h>
#include <math.h>
#include <stdint.h>

// ---------------------------------------------------------------------------
// EfficientSelfAttention (PVT SRA): B=4, N=4096 (64x64), C=512, heads=8,
// head_dim=64, SR=2 -> N_kv=1024.  fp16 m16n8k16 mma.sync (fp32 accum).
// Round 14: round-11 structure (best known: 288.9us) + attention softmax
// denominator computed by an extra mma against a constant ones fragment
// (removes ~128 cvt/add insts per iter per warp and the final shuffles).
// ---------------------------------------------------------------------------

__device__ __half  g_xt[8388608];   // x as half [16384][512]
__device__ float   g_xr[2097152];   // conv partial z=0 (fp32, +bias)
__device__ float   g_xr2[2097152];  // conv partial z=1
__device__ float   g_xr3[2097152];  // conv partial z=2
__device__ float   g_xr4[2097152];  // conv partial z=3
__device__ __half  g_xrh[2097152];  // LN output half
__device__ __half  g_k[2097152];    // [bh][m][d]
__device__ __half  g_v[2097152];    // TRANSPOSED: [bh][d][m]
__device__ __half  g_att[8388608];  // [b,n, h*64+d]
__device__ uint32_t g_q[4194304];   // Q in fp16 A-fragment order (log2-scaled)
__device__ __half  g_wq[262144];    // W^T [N][K]
__device__ __half  g_wkv[524288];
__device__ __half  g_wp[262144];
__device__ __half  g_wsr[1048576];

#define QSCALE 0.18033688011112042f   // 0.125 * log2(e)

__device__ __forceinline__ uint32_t pack2(float a, float b) {
    __half2 h = __floats2half2_rn(a, b);
    return *(uint32_t*)&h;
}
__device__ __forceinline__ uint32_t h2ex2(uint32_t x) {
    uint32_t r;
    asm("ex2.approx.f16x2 %0, %1;" : "=r"(r) : "r"(x));
    return r;
}

__device__ __forceinline__ void mma16(float* c, const uint32_t* a, const uint32_t* b) {
    asm("mma.sync.aligned.m16n8k16.row.col.f32.f16.f16.f32 "
        "{%0,%1,%2,%3}, {%4,%5,%6,%7}, {%8,%9}, {%0,%1,%2,%3};"
        : "+f"(c[0]), "+f"(c[1]), "+f"(c[2]), "+f"(c[3])
        : "r"(a[0]), "r"(a[1]), "r"(a[2]), "r"(a[3]), "r"(b[0]), "r"(b[1]));
}

__device__ __forceinline__ void cp16(uint32_t dst, const void* src) {
    asm volatile("cp.async.cg.shared.global [%0], [%1], 16;" :: "r"(dst), "l"(src));
}
__device__ __forceinline__ void cp_commit() {
    asm volatile("cp.async.commit_group;");
}
template <int N>
__device__ __forceinline__ void cp_wait() {
    asm volatile("cp.async.wait_group %0;" :: "n"(N));
}

// ---------------------------------------------------------------------------
// Merged pre-pass: blocks [0,8192) convert x -> half; [8192,10240) transpose
// weights fp32 [K][N] -> half [N][K].
// ---------------------------------------------------------------------------
__global__ void __launch_bounds__(256) prepass(
    const float4* __restrict__ x,
    const float* __restrict__ wq, const float* __restrict__ wkv,
    const float* __restrict__ wp, const float* __restrict__ wsr)
{
    __shared__ float tile[32][33];
    if (blockIdx.x < 8192) {
        int i = blockIdx.x * 256 + threadIdx.x;
        float4 v = x[i];
        uint2 o;
        o.x = pack2(v.x, v.y);
        o.y = pack2(v.z, v.w);
        *(uint2*)(g_xt + (size_t)i * 4) = o;
        return;
    }
    int t = blockIdx.x - 8192;
    const float* src; __half* dst; int K, N, tk, tn;
    if (t < 256)       { src = wq;  dst = g_wq;  K = 512;  N = 512;  tk = t >> 4; tn = t & 15; }
    else if (t < 768)  { t -= 256;  src = wkv; dst = g_wkv; K = 512;  N = 1024; tk = t >> 5; tn = t & 31; }
    else if (t < 1024) { t -= 768;  src = wp;  dst = g_wp;  K = 512;  N = 512;  tk = t >> 4; tn = t & 15; }
    else               { t -= 1024; src = wsr; dst = g_wsr; K = 2048; N = 512;  tk = t >> 4; tn = t & 15; }

    int tx = threadIdx.x & 31, ty = threadIdx.x >> 5;
    int k0 = tk * 32, n0 = tn * 32;
    #pragma unroll
    for (int i = 0; i < 4; i++)
        tile[tx][ty + 8 * i] = src[(size_t)(k0 + ty + 8 * i) * N + n0 + tx];
    __syncthreads();
    #pragma unroll
    for (int i = 0; i < 4; i++) {
        int row = ty + 8 * i;
        dst[(size_t)(n0 + row) * K + k0 + tx] = __float2half_rn(tile[row][tx]);
    }
}

// ---------------------------------------------------------------------------
// WIDE fp16 GEMM: block 128x256, BK=32, 3-stage cp.async ring, 8 warps (2x4),
// warp tile 64x64.
// MODE 0: A=g_xt,  B=g_wq^T -> g_q fragment-order (*QSCALE, +bias, half)
// MODE 3: A=g_att, B=g_wp^T -> Cout fp32 (+bias)
// ---------------------------------------------------------------------------
template <int MODE>
__global__ void __launch_bounds__(256) gemm_wide(
    const float* __restrict__ bias, float* __restrict__ Cout, int K)
{
    extern __shared__ uint32_t smem[];
    const int OB = 3 * 128 * 20;  // 7680

    const int tid = threadIdx.x, lane = tid & 31, warp = tid >> 5;
    const int wm = warp >> 2, wn = warp & 3;
    const int l2 = lane >> 2, l4 = lane & 3;
    const int m0 = blockIdx.y * 128, n0 = blockIdx.x * 256;

    const __half* Ap = (MODE == 3) ? g_att : g_xt;
    const __half* Bp = (MODE == 3) ? g_wp : g_wq;

    const uint32_t sbase = (uint32_t)__cvta_generic_to_shared(smem);

    float acc[4][8][4] = {};

    auto load_tiles = [&](int s, int k0) {
        #pragma unroll
        for (int u = 0; u < 2; u++) {
            int e = u * 256 + tid;
            int row = e >> 2, cw = e & 3;
            cp16(sbase + (uint32_t)(s * 2560 + row * 20 + cw * 4) * 4,
                 Ap + (size_t)(m0 + row) * K + k0 + cw * 8);
        }
        #pragma unroll
        for (int u = 0; u < 4; u++) {
            int e = u * 256 + tid;
            int row = e >> 2, cw = e & 3;
            cp16(sbase + (uint32_t)(OB + s * 5120 + row * 20 + cw * 4) * 4,
                 Bp + (size_t)(n0 + row) * K + k0 + cw * 8);
        }
    };

    const int KT = K >> 5;
    load_tiles(0, 0);
    cp_commit();
    load_tiles(1, 32);
    cp_commit();

    for (int kt = 0; kt < KT; kt++) {
        if (kt < KT - 1) { cp_wait<1>(); } else { cp_wait<0>(); }
        __syncthreads();
        if (kt + 2 < KT) {
            load_tiles((kt + 2) % 3, (kt + 2) * 32);
            cp_commit();
        }
        const int stage = kt % 3;

        const uint32_t* Ab = smem + stage * 2560;
        const uint32_t* Bb = smem + OB + stage * 5120;
        #pragma unroll
        for (int j = 0; j < 2; j++) {
            uint32_t a[4][4], bf[8][2];
            #pragma unroll
            for (int mt = 0; mt < 4; mt++) {
                int r = wm * 64 + mt * 16 + l2;
                a[mt][0] = Ab[r * 20 + j * 8 + l4];
                a[mt][1] = Ab[(r + 8) * 20 + j * 8 + l4];
                a[mt][2] = Ab[r * 20 + j * 8 + l4 + 4];
                a[mt][3] = Ab[(r + 8) * 20 + j * 8 + l4 + 4];
            }
            #pragma unroll
            for (int nt = 0; nt < 8; nt++) {
                int col = wn * 64 + nt * 8 + l2;
                bf[nt][0] = Bb[col * 20 + j * 8 + l4];
                bf[nt][1] = Bb[col * 20 + j * 8 + l4 + 4];
            }
            #pragma unroll
            for (int mt = 0; mt < 4; mt++)
                #pragma unroll
                for (int nt = 0; nt < 8; nt++)
                    mma16(acc[mt][nt], a[mt], bf[nt]);
        }
        __syncthreads();
    }

    #pragma unroll
    for (int mt = 0; mt < 4; mt++) {
        #pragma unroll
        for (int nt = 0; nt < 8; nt++) {
            int r = m0 + wm * 64 + mt * 16 + l2;
            int c = n0 + wn * 64 + nt * 8 + l4 * 2;
            float b0 = bias[c], b1 = bias[c + 1];
            float v00 = acc[mt][nt][0] + b0, v01 = acc[mt][nt][1] + b1;
            float v10 = acc[mt][nt][2] + b0, v11 = acc[mt][nt][3] + b1;
            if (MODE == 0) {
                int b_ = r >> 12, nq = r & 4095;
                int h = c >> 6, d = c & 63;
                int bh = b_ * 8 + h, ntile = nq >> 4;
                int j = d >> 4, wsel = (d >> 3) & 1;
                size_t base = (((size_t)(bh * 256 + ntile) * 4 + j) * 32 + lane) * 4 + wsel * 2;
                g_q[base]     = pack2(v00 * QSCALE, v01 * QSCALE);
                g_q[base + 1] = pack2(v10 * QSCALE, v11 * QSCALE);
            } else {
                *(float2*)(Cout + (size_t)r * 512 + c) = make_float2(v00, v01);
                *(float2*)(Cout + (size_t)(r + 8) * 512 + c) = make_float2(v10, v11);
            }
        }
    }
}

// ---------------------------------------------------------------------------
// Narrow fp16 GEMM: block 128x128, BK=32, 3-stage ring, warp tile 32x64.
// MODE 1: A=g_xt (conv patch gather), B=g_wsr^T -> split-K z=0..3 partials
// MODE 2: A=g_xrh, B=g_wkv^T -> g_k / g_v (transposed) (+bias)
// ---------------------------------------------------------------------------
template <int MODE>
__global__ void __launch_bounds__(256) gemm_h(
    const float* __restrict__ bias, int Kfull)
{
    extern __shared__ uint32_t smem[];
    const int OB = 3 * 128 * 20;

    const int tid = threadIdx.x, lane = tid & 31, warp = tid >> 5;
    const int wm = warp >> 1, wn = warp & 1;
    const int l2 = lane >> 2, l4 = lane & 3;
    const int m0 = blockIdx.y * 128, n0 = blockIdx.x * 128;
    const int kz0 = (MODE == 1) ? (int)blockIdx.z * 512 : 0;
    const int Kblk = (MODE == 1) ? 512 : Kfull;

    const __half* Ap = (MODE == 2) ? g_xrh : g_xt;
    const __half* Bp = (MODE == 1) ? g_wsr : g_wkv;

    const uint32_t sbase = (uint32_t)__cvta_generic_to_shared(smem);

    float acc[2][8][4] = {};

    auto load_tiles = [&](int s, int kg) {
        #pragma unroll
        for (int u = 0; u < 2; u++) {
            int e = u * 256 + tid;
            int row = e >> 2, cw = e & 3;
            const __half* src;
            if (MODE == 1) {
                int m = m0 + row;
                int b = m >> 10, rem = m & 1023;
                int oh = rem >> 5, ow = rem & 31;
                int k = kg + cw * 8;
                int di = k >> 10, dj = (k >> 9) & 1, c = k & 511;
                int grow = (b << 12) + (((oh << 1) + di) << 6) + (ow << 1) + dj;
                src = Ap + (size_t)grow * 512 + c;
            } else {
                src = Ap + (size_t)(m0 + row) * Kfull + kg + cw * 8;
            }
            cp16(sbase + (uint32_t)(s * 2560 + row * 20 + cw * 4) * 4, src);
        }
        #pragma unroll
        for (int u = 0; u < 2; u++) {
            int e = u * 256 + tid;
            int row = e >> 2, cw = e & 3;
            cp16(sbase + (uint32_t)(OB + s * 2560 + row * 20 + cw * 4) * 4,
                 Bp + (size_t)(n0 + row) * Kfull + kg + cw * 8);
        }
    };

    const int KT = Kblk >> 5;
    load_tiles(0, kz0);
    cp_commit();
    load_tiles(1, kz0 + 32);
    cp_commit();

    for (int kt = 0; kt < KT; kt++) {
        if (kt < KT - 1) { cp_wait<1>(); } else { cp_wait<0>(); }
        __syncthreads();
        if (kt + 2 < KT) {
            load_tiles((kt + 2) % 3, kz0 + (kt + 2) * 32);
            cp_commit();
        }
        const int stage = kt % 3;

        const uint32_t* Ab = smem + stage * 2560;
        const uint32_t* Bb = smem + OB + stage * 2560;
        #pragma unroll
        for (int j = 0; j < 2; j++) {
            uint32_t a[2][4], bf[8][2];
            #pragma unroll
            for (int mt = 0; mt < 2; mt++) {
                int r = wm * 32 + mt * 16 + l2;
                a[mt][0] = Ab[r * 20 + j * 8 + l4];
                a[mt][1] = Ab[(r + 8) * 20 + j * 8 + l4];
                a[mt][2] = Ab[r * 20 + j * 8 + l4 + 4];
                a[mt][3] = Ab[(r + 8) * 20 + j * 8 + l4 + 4];
            }
            #pragma unroll
            for (int nt = 0; nt < 8; nt++) {
                int col = wn * 64 + nt * 8 + l2;
                bf[nt][0] = Bb[col * 20 + j * 8 + l4];
                bf[nt][1] = Bb[col * 20 + j * 8 + l4 + 4];
            }
            #pragma unroll
            for (int mt = 0; mt < 2; mt++)
                #pragma unroll
                for (int nt = 0; nt < 8; nt++)
                    mma16(acc[mt][nt], a[mt], bf[nt]);
        }
        __syncthreads();
    }

    #pragma unroll
    for (int mt = 0; mt < 2; mt++) {
        #pragma unroll
        for (int nt = 0; nt < 8; nt++) {
            int r = m0 + wm * 32 + mt * 16 + l2;
            int c = n0 + wn * 64 + nt * 8 + l4 * 2;
            if (MODE == 1) {
                float b0 = 0.0f, b1 = 0.0f;
                int z = blockIdx.z;
                if (z == 0) { b0 = bias[c]; b1 = bias[c + 1]; }
                float* dst = (z == 0) ? g_xr : (z == 1) ? g_xr2
                           : (z == 2) ? g_xr3 : g_xr4;
                *(float2*)(dst + (size_t)r * 512 + c) =
                    make_float2(acc[mt][nt][0] + b0, acc[mt][nt][1] + b1);
                *(float2*)(dst + (size_t)(r + 8) * 512 + c) =
                    make_float2(acc[mt][nt][2] + b0, acc[mt][nt][3] + b1);
            } else {
                float b0 = bias[c], b1 = bias[c + 1];
                float v00 = acc[mt][nt][0] + b0, v01 = acc[mt][nt][1] + b1;
                float v10 = acc[mt][nt][2] + b0, v11 = acc[mt][nt][3] + b1;
                int cc = c & 511, h = cc >> 6, d = cc & 63;
                int b_ = r >> 10, mi = r & 1023;
                size_t bhO = (size_t)(b_ * 8 + h) * 65536;
                if (c < 512) {
                    *(uint32_t*)(g_k + bhO + (size_t)mi * 64 + d) = pack2(v00, v01);
                    *(uint32_t*)(g_k + bhO + (size_t)(mi + 8) * 64 + d) = pack2(v10, v11);
                } else {
                    g_v[bhO + (size_t)d * 1024 + mi]           = __float2half_rn(v00);
                    g_v[bhO + (size_t)(d + 1) * 1024 + mi]     = __float2half_rn(v01);
                    g_v[bhO + (size_t)d * 1024 + mi + 8]       = __float2half_rn(v10);
                    g_v[bhO + (size_t)(d + 1) * 1024 + mi + 8] = __float2half_rn(v11);
                }
            }
        }
    }
}

// ---------------------------------------------------------------------------
// LayerNorm: sums 4 split-K partials, writes g_xrh (half). eps=1e-3.
// ---------------------------------------------------------------------------
__global__ void __launch_bounds__(128) ln_kernel(
    const float* __restrict__ gamma, const float* __restrict__ beta)
{
    int row = blockIdx.x;
    int t = threadIdx.x;
    size_t off = (size_t)row * 512 + t * 4;

    float4 v  = *(const float4*)(g_xr + off);
    float4 v2 = *(const float4*)(g_xr2 + off);
    float4 v3 = *(const float4*)(g_xr3 + off);
    float4 v4 = *(const float4*)(g_xr4 + off);
    v.x += v2.x + v3.x + v4.x;
    v.y += v2.y + v3.y + v4.y;
    v.z += v2.z + v3.z + v4.z;
    v.w += v2.w + v3.w + v4.w;

    float s  = v.x + v.y + v.z + v.w;
    float s2 = v.x * v.x + v.y * v.y + v.z * v.z + v.w * v.w;

    #pragma unroll
    for (int o = 16; o > 0; o >>= 1) {
        s  += __shfl_xor_sync(0xffffffffu, s, o);
        s2 += __shfl_xor_sync(0xffffffffu, s2, o);
    }
    __shared__ float red[2][4];
    int w = t >> 5;
    if ((t & 31) == 0) { red[0][w] = s; red[1][w] = s2; }
    __syncthreads();
    s  = red[0][0] + red[0][1] + red[0][2] + red[0][3];
    s2 = red[1][0] + red[1][1] + red[1][2] + red[1][3];

    float mu  = s * (1.0f / 512.0f);
    float var = s2 * (1.0f / 512.0f) - mu * mu;
    float inv = rsqrtf(var + 1e-3f);

    float4 g  = *(const float4*)(gamma + t * 4);
    float4 be = *(const float4*)(beta + t * 4);
    uint2 o;
    o.x = pack2((v.x - mu) * inv * g.x + be.x, (v.y - mu) * inv * g.y + be.y);
    o.y = pack2((v.z - mu) * inv * g.z + be.z, (v.w - mu) * inv * g.w + be.w);
    *(uint2*)(g_xrh + off) = o;
}

// ---------------------------------------------------------------------------
// Flash attention fp16: 128 threads / 4 warps, each warp owns 32 q rows
// (two 16-row fragment groups); K/V fragments reused across both groups.
// Softmax denominator l computed via an extra mma against a constant ones
// B-fragment (fp32 accum; no cvt/add chain, no final shuffles).
// BQ=128, BKV=64, log2-domain ex2 softmax, 3-stage cp.async ring.
// smem u32: K[3][64][36] | V[3][64][36] = 55296 B.
// ---------------------------------------------------------------------------
__global__ void __launch_bounds__(128) attn_h()
{
    extern __shared__ uint32_t sm[];
    const int VOFF = 3 * 64 * 36;

    const int tid = threadIdx.x, lane = tid & 31, warp = tid >> 5;  // warp 0..3
    const int l2 = lane >> 2, l4 = lane & 3;
    const int bh = blockIdx.y, b = bh >> 3, h = bh & 7;
    const int q0 = blockIdx.x * 128;

    const __half* Kg = g_k + (size_t)bh * 65536;
    const __half* Vg = g_v + (size_t)bh * 65536;  // [d][m]

    const uint32_t sbase = (uint32_t)__cvta_generic_to_shared(sm);

    auto loadKV = [&](int s, int kv0) {
        #pragma unroll
        for (int u = 0; u < 4; u++) {
            int e = u * 128 + tid;
            int r = e >> 3, cw = e & 7;
            cp16(sbase + (uint32_t)(s * 2304 + r * 36 + cw * 4) * 4,
                 Kg + (size_t)(kv0 + r) * 64 + cw * 8);
            cp16(sbase + (uint32_t)(VOFF + s * 2304 + r * 36 + cw * 4) * 4,
                 Vg + (size_t)r * 1024 + kv0 + cw * 8);
        }
    };

    loadKV(0, 0);
    cp_commit();
    loadKV(1, 64);
    cp_commit();

    // Q fragments for two 16-row groups: tiles 2*warp, 2*warp+1
    uint32_t qf[2][4][4];
    {
        const uint4* Qf = (const uint4*)g_q;
        #pragma unroll
        for (int g = 0; g < 2; g++) {
            size_t base = ((size_t)(bh * 256 + blockIdx.x * 8 + warp * 2 + g) * 4) * 32;
            #pragma unroll
            for (int j = 0; j < 4; j++) {
                uint4 v = Qf[base + j * 32 + lane];
                qf[g][j][0] = v.x; qf[g][j][1] = v.y;
                qf[g][j][2] = v.z; qf[g][j][3] = v.w;
            }
        }
    }

    float oacc[2][8][4] = {};
    float lsum[2][4] = {};
    const uint32_t onesf[2] = {0x3C003C00u, 0x3C003C00u};  // half2(1,1) x2

    for (int kc = 0; kc < 16; kc++) {
        if (kc < 15) { cp_wait<1>(); } else { cp_wait<0>(); }
        __syncthreads();
        if (kc + 2 < 16) {
            loadKV((kc + 2) % 3, (kc + 2) * 64);
            cp_commit();
        }
        const int stage = kc % 3;

        // S = Q K^T (log2 domain); K fragments shared across both row groups
        float sacc[2][8][4] = {};
        const uint32_t* Kb = sm + stage * 2304;
        #pragma unroll
        for (int j = 0; j < 4; j++) {
            uint32_t bfr[8][2];
            #pragma unroll
            for (int nt = 0; nt < 8; nt++) {
                int kvi = nt * 8 + l2;
                bfr[nt][0] = Kb[kvi * 36 + j * 8 + l4];
                bfr[nt][1] = Kb[kvi * 36 + j * 8 + l4 + 4];
            }
            #pragma unroll
            for (int g = 0; g < 2; g++)
                #pragma unroll
                for (int nt = 0; nt < 8; nt++)
                    mma16(sacc[g][nt], qf[g][j], bfr[nt]);
        }

        // O += P V ; l += P @ ones (extra mma, constant B fragment)
        const uint32_t* Vb = sm + VOFF + stage * 2304;
        #pragma unroll
        for (int j = 0; j < 4; j++) {
            uint32_t vfr[8][2];
            #pragma unroll
            for (int nt = 0; nt < 8; nt++) {
                int d = nt * 8 + l2;
                vfr[nt][0] = Vb[d * 36 + j * 8 + l4];
                vfr[nt][1] = Vb[d * 36 + j * 8 + l4 + 4];
            }
            #pragma unroll
            for (int g = 0; g < 2; g++) {
                uint32_t a[4];
                a[0] = h2ex2(pack2(sacc[g][2 * j][0],     sacc[g][2 * j][1]));
                a[1] = h2ex2(pack2(sacc[g][2 * j][2],     sacc[g][2 * j][3]));
                a[2] = h2ex2(pack2(sacc[g][2 * j + 1][0], sacc[g][2 * j + 1][1]));
                a[3] = h2ex2(pack2(sacc[g][2 * j + 1][2], sacc[g][2 * j + 1][3]));
                #pragma unroll
                for (int nt = 0; nt < 8; nt++)
                    mma16(oacc[g][nt], a, vfr[nt]);
                mma16(lsum[g], a, onesf);
            }
        }
    }

    // normalize and write (lsum c[0]=row l2 sum, c[2]=row l2+8 sum)
    #pragma unroll
    for (int g = 0; g < 2; g++) {
        float i0 = 1.0f / lsum[g][0];
        float i1 = 1.0f / lsum[g][2];
        int n = q0 + warp * 32 + g * 16 + l2;
        #pragma unroll
        for (int nt = 0; nt < 8; nt++) {
            int d = nt * 8 + l4 * 2;
            *(uint32_t*)(g_att + ((size_t)(b * 4096 + n) * 512 + h * 64 + d)) =
                pack2(oacc[g][nt][0] * i0, oacc[g][nt][1] * i0);
            *(uint32_t*)(g_att + ((size_t)(b * 4096 + n + 8) * 512 + h * 64 + d)) =
                pack2(oacc[g][nt][2] * i1, oacc[g][nt][3] * i1);
        }
    }
}

// ---------------------------------------------------------------------------
// Launcher
// ---------------------------------------------------------------------------
extern "C" void kernel_launch(void* const* d_in, const int* in_sizes, int n_in,
                              void* d_out, int out_size)
{
    const float *x = 0, *Wq = 0, *bq = 0, *Wkv = 0, *bkv = 0, *Wp = 0, *bp = 0;
    const float *srk = 0, *srb = 0, *gma = 0, *bta = 0;
    const float* s512[5] = {0, 0, 0, 0, 0};
    const float* s256k[2] = {0, 0};
    int n512 = 0, nbig = 0;

    for (int i = 0; i < n_in; i++) {
        int sz = in_sizes[i];
        const float* p = (const float*)d_in[i];
        if (sz == 8388608 && !x) x = p;
        else if (sz == 262144 && nbig < 2) s256k[nbig++] = p;
        else if (sz == 524288) Wkv = p;
        else if (sz == 1048576) srk = p;
        else if (sz == 1024) bkv = p;
        else if (sz == 512 && n512 < 5) s512[n512++] = p;
    }
    Wq = s256k[0]; Wp = s256k[1];
    bq = s512[0]; bp = s512[1]; srb = s512[2]; gma = s512[3]; bta = s512[4];
    float* out = (float*)d_out;

    const int wide_smem = (3 * 128 * 20 + 3 * 256 * 20) * 4;  // 92160
    const int nar_smem  = (3 * 128 * 20 + 3 * 128 * 20) * 4;  // 61440
    const int attn_smem = 6 * 64 * 36 * 4;                    // 55296
    cudaFuncSetAttribute(gemm_wide<0>, cudaFuncAttributeMaxDynamicSharedMemorySize, wide_smem);
    cudaFuncSetAttribute(gemm_wide<3>, cudaFuncAttributeMaxDynamicSharedMemorySize, wide_smem);
    cudaFuncSetAttribute(gemm_h<1>, cudaFuncAttributeMaxDynamicSharedMemorySize, nar_smem);
    cudaFuncSetAttribute(gemm_h<2>, cudaFuncAttributeMaxDynamicSharedMemorySize, nar_smem);
    cudaFuncSetAttribute(attn_h,  cudaFuncAttributeMaxDynamicSharedMemorySize, attn_smem);

    // merged pre-pass (x convert + weight transpose)
    prepass<<<10240, 256>>>((const float4*)x, Wq, Wkv, Wp, srk);
    // Q projection -> fragment-order g_q (log2-domain scale)
    gemm_wide<0><<<dim3(2, 128), 256, wide_smem>>>(bq, nullptr, 512);
    // SR conv as patch GEMM, split-K=4
    gemm_h<1><<<dim3(4, 32, 4), 256, nar_smem>>>(srb, 2048);
    // LayerNorm (sums 4 partials) -> g_xrh
    ln_kernel<<<4096, 128>>>(gma, bta);
    // KV projection -> g_k, g_v (V transposed)
    gemm_h<2><<<dim3(8, 32), 256, nar_smem>>>(bkv, 512);
    // attention (128 threads, 4 warps x 32 rows)
    attn_h<<<dim3(32, 32), 128, attn_smem>>>();
    // output projection -> d_out fp32
    gemm_wide<3><<<dim3(2, 128), 256, wide_smem>>>(bp, out, 512);
    (void)out_size;
}